// round 1
// baseline (speedup 1.0000x reference)
#include <cuda_runtime.h>

#define MAXPTS 50000
#define NBLK 296

// ---------------- scratch (no allocation allowed) ----------------
__device__ float  g_y1[MAXPTS * 32];    // unary1 pre-BN
__device__ float  g_xc1[MAXPTS * 32];   // unary1 post BN+lrelu
__device__ float  g_y2[MAXPTS * 32];    // conv output pre-BN
__device__ float  g_z[MAXPTS * 128];    // unary2 pre-BN
__device__ double g_acc[384];           // [0:32) sum1 [32:64) sq1 [64:96) sumC [96:128) sqC [128:256) sum3 [256:384) sq3
__device__ float  g_a1[32], g_c1[32], g_aC[32], g_cC[32], g_a3[128], g_c3[128];

__device__ __forceinline__ float lrelu(float x) { return fmaxf(x, 0.1f * x); }

// ---------------- K0: zero accumulators ----------------
__global__ void kpi_zero_kernel() {
    int t = threadIdx.x;
    if (t < 384) g_acc[t] = 0.0;
}

// ---------------- K1: y1 = s_feats @ w_u1  (M,128)x(128,32), + column stats ----------------
__global__ void __launch_bounds__(256) kpi_u1_kernel(const float* __restrict__ sf,
                                                     const float* __restrict__ w, int M) {
    __shared__ __align__(16) float w_s[4096];        // [c2][c] 128x32
    __shared__ __align__(16) float rows_s[32][128];
    __shared__ float red_s[8][32];
    int tid = threadIdx.x;
    for (int i = tid; i < 4096; i += 256) w_s[i] = w[i];
    int c = tid & 31, rq = tid >> 5;
    float fsum = 0.f, fsq = 0.f;
    int ntile = (M + 31) >> 5;
    for (int T = blockIdx.x; T < ntile; T += gridDim.x) {
        int base = T << 5;
        __syncthreads();
        for (int i = tid; i < 1024; i += 256) {
            int r = i >> 5, c4 = i & 31;
            int m = base + r;
            float4 v = make_float4(0.f, 0.f, 0.f, 0.f);
            if (m < M) v = reinterpret_cast<const float4*>(sf)[m * 32 + c4];
            reinterpret_cast<float4*>(&rows_s[r][0])[c4] = v;
        }
        __syncthreads();
        float a0 = 0.f, a1 = 0.f, a2 = 0.f, a3 = 0.f;
#pragma unroll
        for (int c2 = 0; c2 < 128; c2 += 4) {
            float w0 = w_s[c2 * 32 + c], w1 = w_s[(c2 + 1) * 32 + c];
            float w2 = w_s[(c2 + 2) * 32 + c], w3 = w_s[(c2 + 3) * 32 + c];
            float4 r0 = reinterpret_cast<const float4*>(&rows_s[rq][0])[c2 >> 2];
            float4 r1 = reinterpret_cast<const float4*>(&rows_s[rq + 8][0])[c2 >> 2];
            float4 r2 = reinterpret_cast<const float4*>(&rows_s[rq + 16][0])[c2 >> 2];
            float4 r3 = reinterpret_cast<const float4*>(&rows_s[rq + 24][0])[c2 >> 2];
            a0 = fmaf(r0.x, w0, a0); a0 = fmaf(r0.y, w1, a0); a0 = fmaf(r0.z, w2, a0); a0 = fmaf(r0.w, w3, a0);
            a1 = fmaf(r1.x, w0, a1); a1 = fmaf(r1.y, w1, a1); a1 = fmaf(r1.z, w2, a1); a1 = fmaf(r1.w, w3, a1);
            a2 = fmaf(r2.x, w0, a2); a2 = fmaf(r2.y, w1, a2); a2 = fmaf(r2.z, w2, a2); a2 = fmaf(r2.w, w3, a2);
            a3 = fmaf(r3.x, w0, a3); a3 = fmaf(r3.y, w1, a3); a3 = fmaf(r3.z, w2, a3); a3 = fmaf(r3.w, w3, a3);
        }
        int m;
        m = base + rq;      if (m < M) { g_y1[m * 32 + c] = a0; fsum += a0; fsq += a0 * a0; }
        m = base + rq + 8;  if (m < M) { g_y1[m * 32 + c] = a1; fsum += a1; fsq += a1 * a1; }
        m = base + rq + 16; if (m < M) { g_y1[m * 32 + c] = a2; fsum += a2; fsq += a2 * a2; }
        m = base + rq + 24; if (m < M) { g_y1[m * 32 + c] = a3; fsum += a3; fsq += a3 * a3; }
    }
    __syncthreads();
    red_s[rq][c] = fsum; __syncthreads();
    if (rq == 0) {
        float s = 0.f;
#pragma unroll
        for (int i = 0; i < 8; i++) s += red_s[i][c];
        atomicAdd(&g_acc[c], (double)s);
    }
    __syncthreads();
    red_s[rq][c] = fsq; __syncthreads();
    if (rq == 0) {
        float s = 0.f;
#pragma unroll
        for (int i = 0; i < 8; i++) s += red_s[i][c];
        atomicAdd(&g_acc[32 + c], (double)s);
    }
}

// ---------------- finalize: a = g/sqrt(var+eps), c = b - mean*a ----------------
__global__ void kpi_finalize_kernel(int stage, const float* __restrict__ g,
                                    const float* __restrict__ b, double invM) {
    int t = threadIdx.x;
    const double* sum; const double* sq; float* a; float* cc; int n;
    if (stage == 0)      { sum = g_acc;       sq = g_acc + 32;  a = g_a1; cc = g_c1; n = 32; }
    else if (stage == 1) { sum = g_acc + 64;  sq = g_acc + 96;  a = g_aC; cc = g_cC; n = 32; }
    else                 { sum = g_acc + 128; sq = g_acc + 256; a = g_a3; cc = g_c3; n = 128; }
    if (t < n) {
        double mean = sum[t] * invM;
        double var  = sq[t] * invM - mean * mean;
        float inv = (float)(1.0 / sqrt(var + 1e-5));
        float av = g[t] * inv;
        a[t]  = av;
        cc[t] = b[t] - (float)mean * av;
    }
}

// ---------------- K2b: xc1 = lrelu(bn(y1)) ----------------
__global__ void kpi_xform_kernel(int n4) {
    int i = blockIdx.x * blockDim.x + threadIdx.x;
    int stride = gridDim.x * blockDim.x;
    for (; i < n4; i += stride) {
        float4 v = reinterpret_cast<const float4*>(g_y1)[i];
        int c = (i << 2) & 31;
        float4 r;
        r.x = lrelu(fmaf(v.x, g_a1[c + 0], g_c1[c + 0]));
        r.y = lrelu(fmaf(v.y, g_a1[c + 1], g_c1[c + 1]));
        r.z = lrelu(fmaf(v.z, g_a1[c + 2], g_c1[c + 2]));
        r.w = lrelu(fmaf(v.w, g_a1[c + 3], g_c1[c + 3]));
        reinterpret_cast<float4*>(g_xc1)[i] = r;
    }
}

// ---------------- K3: KPInv conv (warp per point) + conv column stats ----------------
__global__ void __launch_bounds__(256) kpi_conv_kernel(const float* __restrict__ qp,
                                                       const float* __restrict__ sp,
                                                       const int* __restrict__ nidx,
                                                       const float* __restrict__ kp,
                                                       const float* __restrict__ wg1,
                                                       const float* __restrict__ bg1,
                                                       const float* __restrict__ wg2,
                                                       const float* __restrict__ bg2, int M) {
    __shared__ __align__(16) float nfeat_s[8][32][32]; // 32 KB
    __shared__ float omg_s[8][32][2];
    __shared__ float center_s[8][32];
    __shared__ float hid_s[8][8];
    __shared__ float wv_s[8][32];
    __shared__ float kp_s[16][4];     // x,y,z,|k|^2
    __shared__ float wg1_s[32][8];
    __shared__ float bg1_s[8];
    __shared__ float wg2_s[8][32];    // 30 used per row
    __shared__ float bg2_s[32];

    int tid = threadIdx.x, wid = tid >> 5, t = tid & 31;
    // load small params
    if (tid < 15) {
        float kx = kp[3 * tid], ky = kp[3 * tid + 1], kz = kp[3 * tid + 2];
        kp_s[tid][0] = kx; kp_s[tid][1] = ky; kp_s[tid][2] = kz;
        kp_s[tid][3] = kx * kx + ky * ky + kz * kz;
    }
    for (int i = tid; i < 256; i += 256) wg1_s[i >> 3][i & 7] = wg1[i];
    if (tid < 8) bg1_s[tid] = bg1[tid];
    if (tid < 240) wg2_s[tid / 30][tid % 30] = wg2[tid];
    if (tid < 30) bg2_s[tid] = bg2[tid];
    __syncthreads();

    float fsum = 0.f, fsq = 0.f;
    for (int m = blockIdx.x * 8 + wid; m < M; m += gridDim.x * 8) {
        int j = nidx[m * 32 + t];
        float qx = qp[3 * m], qy = qp[3 * m + 1], qz = qp[3 * m + 2];
        float nx = sp[3 * j] - qx, ny = sp[3 * j + 1] - qy, nz = sp[3 * j + 2] - qz;
        float nn = nx * nx + ny * ny + nz * nz;
        float infl[15];
#pragma unroll
        for (int k = 0; k < 15; k++) {
            float d2 = nn + kp_s[k][3]
                     - 2.f * (nx * kp_s[k][0] + ny * kp_s[k][1] + nz * kp_s[k][2]);
            infl[k] = fmaxf(1.f - sqrtf(fmaxf(d2, 0.f)), 0.f);
        }
        // gather neighbor features (post unary1 activation); lane t = channel t
        float cmax = -3.4e38f;
#pragma unroll
        for (int h = 0; h < 32; h++) {
            int jh = __shfl_sync(0xffffffffu, j, h);
            float v = g_xc1[jh * 32 + t];
            nfeat_s[wid][h][t] = v;
            cmax = fmaxf(cmax, v);
        }
        center_s[wid][t] = cmax;
        __syncwarp();
        // hidden = lrelu(center @ w_g1 + b_g1), lanes 0..7
        if (t < 8) {
            float a = bg1_s[t];
#pragma unroll
            for (int c2 = 0; c2 < 32; c2++) a = fmaf(center_s[wid][c2], wg1_s[c2][t], a);
            hid_s[wid][t] = lrelu(a);
        }
        __syncwarp();
        // w = hidden @ w_g2 + b_g2, lanes 0..29  (w[k,g] = w[2k+g])
        if (t < 30) {
            float a = bg2_s[t];
#pragma unroll
            for (int k8 = 0; k8 < 8; k8++) a = fmaf(hid_s[wid][k8], wg2_s[k8][t], a);
            wv_s[wid][t] = a;
        }
        __syncwarp();
        // omega[h,g] = sum_k w[k,g] * infl[h,k], lane t = neighbor h
        float om0 = 0.f, om1 = 0.f;
#pragma unroll
        for (int k = 0; k < 15; k++) {
            om0 = fmaf(wv_s[wid][2 * k], infl[k], om0);
            om1 = fmaf(wv_s[wid][2 * k + 1], infl[k], om1);
        }
        omg_s[wid][t][0] = om0;
        omg_s[wid][t][1] = om1;
        __syncwarp();
        // out[c] = sum_h omega[h, c>>4] * nfeat[h,c], lane t = channel c
        int grp = t >> 4;
        float out = 0.f;
#pragma unroll
        for (int h = 0; h < 32; h++) out = fmaf(omg_s[wid][h][grp], nfeat_s[wid][h][t], out);
        g_y2[m * 32 + t] = out;
        fsum += out; fsq += out * out;
        __syncwarp();
    }
    // block-reduce column stats (column == lane id)
    __syncthreads();
    center_s[wid][t] = fsum; __syncthreads();
    if (wid == 0) {
        float s = 0.f;
#pragma unroll
        for (int i = 0; i < 8; i++) s += center_s[i][t];
        atomicAdd(&g_acc[64 + t], (double)s);
    }
    __syncthreads();
    center_s[wid][t] = fsq; __syncthreads();
    if (wid == 0) {
        float s = 0.f;
#pragma unroll
        for (int i = 0; i < 8; i++) s += center_s[i][t];
        atomicAdd(&g_acc[96 + t], (double)s);
    }
}

// ---------------- K5: z = lrelu(bn(y2)) @ w_u2  (M,32)x(32,128), + column stats ----------------
__global__ void __launch_bounds__(256) kpi_u2_kernel(const float* __restrict__ w, int M) {
    __shared__ __align__(16) float w_s[4096];     // [c2][j] 32x128
    __shared__ __align__(16) float xs[8][32];
    __shared__ float red_s[2][128];
    int tid = threadIdx.x;
    for (int i = tid; i < 4096; i += 256) w_s[i] = w[i];
    int j = tid & 127, rr = tid >> 7;
    float fsum = 0.f, fsq = 0.f;
    int ntile = (M + 7) >> 3;
    for (int T = blockIdx.x; T < ntile; T += gridDim.x) {
        int base = T << 3;
        __syncthreads();
        {
            int r = tid >> 5, cc = tid & 31;
            int m = base + r;
            float v = 0.f;
            if (m < M) {
                v = g_y2[m * 32 + cc];
                v = lrelu(fmaf(v, g_aC[cc], g_cC[cc]));
            }
            xs[r][cc] = v;
        }
        __syncthreads();
        float a0 = 0.f, a1 = 0.f, a2 = 0.f, a3 = 0.f;
#pragma unroll
        for (int c2 = 0; c2 < 32; c2 += 4) {
            float4 x0 = reinterpret_cast<const float4*>(&xs[rr][0])[c2 >> 2];
            float4 x1 = reinterpret_cast<const float4*>(&xs[rr + 2][0])[c2 >> 2];
            float4 x2 = reinterpret_cast<const float4*>(&xs[rr + 4][0])[c2 >> 2];
            float4 x3 = reinterpret_cast<const float4*>(&xs[rr + 6][0])[c2 >> 2];
            float w0 = w_s[c2 * 128 + j], w1 = w_s[(c2 + 1) * 128 + j];
            float w2 = w_s[(c2 + 2) * 128 + j], w3 = w_s[(c2 + 3) * 128 + j];
            a0 = fmaf(x0.x, w0, a0); a0 = fmaf(x0.y, w1, a0); a0 = fmaf(x0.z, w2, a0); a0 = fmaf(x0.w, w3, a0);
            a1 = fmaf(x1.x, w0, a1); a1 = fmaf(x1.y, w1, a1); a1 = fmaf(x1.z, w2, a1); a1 = fmaf(x1.w, w3, a1);
            a2 = fmaf(x2.x, w0, a2); a2 = fmaf(x2.y, w1, a2); a2 = fmaf(x2.z, w2, a2); a2 = fmaf(x2.w, w3, a2);
            a3 = fmaf(x3.x, w0, a3); a3 = fmaf(x3.y, w1, a3); a3 = fmaf(x3.z, w2, a3); a3 = fmaf(x3.w, w3, a3);
        }
        int m;
        m = base + rr;     if (m < M) { g_z[m * 128 + j] = a0; fsum += a0; fsq += a0 * a0; }
        m = base + rr + 2; if (m < M) { g_z[m * 128 + j] = a1; fsum += a1; fsq += a1 * a1; }
        m = base + rr + 4; if (m < M) { g_z[m * 128 + j] = a2; fsum += a2; fsq += a2 * a2; }
        m = base + rr + 6; if (m < M) { g_z[m * 128 + j] = a3; fsum += a3; fsq += a3 * a3; }
    }
    __syncthreads();
    red_s[rr][j] = fsum; __syncthreads();
    if (rr == 0) atomicAdd(&g_acc[128 + j], (double)(red_s[0][j] + red_s[1][j]));
    __syncthreads();
    red_s[rr][j] = fsq; __syncthreads();
    if (rr == 0) atomicAdd(&g_acc[256 + j], (double)(red_s[0][j] + red_s[1][j]));
}

// ---------------- K7: out = lrelu(bn(z) + s_feats) ----------------
__global__ void kpi_final_kernel(const float* __restrict__ sf, float* __restrict__ out, int n4) {
    int i = blockIdx.x * blockDim.x + threadIdx.x;
    int stride = gridDim.x * blockDim.x;
    for (; i < n4; i += stride) {
        float4 z = reinterpret_cast<const float4*>(g_z)[i];
        float4 s = reinterpret_cast<const float4*>(sf)[i];
        int c = (i << 2) & 127;
        float4 r;
        r.x = lrelu(fmaf(z.x, g_a3[c + 0], g_c3[c + 0]) + s.x);
        r.y = lrelu(fmaf(z.y, g_a3[c + 1], g_c3[c + 1]) + s.y);
        r.z = lrelu(fmaf(z.z, g_a3[c + 2], g_c3[c + 2]) + s.z);
        r.w = lrelu(fmaf(z.w, g_a3[c + 3], g_c3[c + 3]) + s.w);
        reinterpret_cast<float4*>(out)[i] = r;
    }
}

// ---------------- launch ----------------
extern "C" void kernel_launch(void* const* d_in, const int* in_sizes, int n_in,
                              void* d_out, int out_size) {
    const float* q_pts   = (const float*)d_in[0];
    const float* s_pts   = (const float*)d_in[1];
    const float* s_feats = (const float*)d_in[2];
    const int*   nidx    = (const int*)d_in[3];
    const float* kp      = (const float*)d_in[4];
    const float* w_u1    = (const float*)d_in[5];
    const float* g_u1    = (const float*)d_in[6];
    const float* b_u1    = (const float*)d_in[7];
    const float* w_g1    = (const float*)d_in[8];
    const float* b_g1    = (const float*)d_in[9];
    const float* w_g2    = (const float*)d_in[10];
    const float* b_g2    = (const float*)d_in[11];
    const float* g_c     = (const float*)d_in[12];
    const float* b_c     = (const float*)d_in[13];
    const float* w_u2    = (const float*)d_in[14];
    const float* g_u2    = (const float*)d_in[15];
    const float* b_u2    = (const float*)d_in[16];
    float* out = (float*)d_out;

    int M = in_sizes[0] / 3;
    double invM = 1.0 / (double)M;

    kpi_zero_kernel<<<1, 384>>>();
    kpi_u1_kernel<<<NBLK, 256>>>(s_feats, w_u1, M);
    kpi_finalize_kernel<<<1, 128>>>(0, g_u1, b_u1, invM);
    kpi_xform_kernel<<<NBLK, 256>>>(M * 8);
    kpi_conv_kernel<<<NBLK, 256>>>(q_pts, s_pts, nidx, kp, w_g1, b_g1, w_g2, b_g2, M);
    kpi_finalize_kernel<<<1, 128>>>(1, g_c, b_c, invM);
    kpi_u2_kernel<<<NBLK, 256>>>(w_u2, M);
    kpi_finalize_kernel<<<1, 128>>>(2, g_u2, b_u2, invM);
    kpi_final_kernel<<<1184, 256>>>(s_feats, out, M * 32);
}

// round 2
// speedup vs baseline: 1.1335x; 1.1335x over previous
#include <cuda_runtime.h>

#define MAXPTS 50000
#define NBLK 592

// ---------------- scratch (no allocation allowed) ----------------
__device__ float  g_y1[MAXPTS * 32];    // unary1 pre-BN
__device__ float  g_y2[MAXPTS * 32];    // conv output pre-BN
__device__ float  g_z[MAXPTS * 128];    // unary2 pre-BN
__device__ double g_acc[384];           // [0:32) sum1 [32:64) sq1 [64:96) sumC [96:128) sqC [128:256) sum3 [256:384) sq3
__device__ float  g_a1[32], g_c1[32], g_aC[32], g_cC[32], g_a3[128], g_c3[128];

__device__ __forceinline__ float lrelu(float x) { return fmaxf(x, 0.1f * x); }

// ---------------- K0: zero accumulators ----------------
__global__ void kpi_zero_kernel() {
    int t = threadIdx.x;
    if (t < 384) g_acc[t] = 0.0;
}

// ---------------- K1: y1 = s_feats @ w_u1  (M,128)x(128,32), + column stats ----------------
__global__ void __launch_bounds__(256) kpi_u1_kernel(const float* __restrict__ sf,
                                                     const float* __restrict__ w, int M) {
    __shared__ __align__(16) float w_s[4096];        // [c2][c] 128x32
    __shared__ __align__(16) float rows_s[32][128];
    __shared__ float red_s[8][32];
    int tid = threadIdx.x;
    for (int i = tid; i < 4096; i += 256) w_s[i] = w[i];
    int c = tid & 31, rq = tid >> 5;
    float fsum = 0.f, fsq = 0.f;
    int ntile = (M + 31) >> 5;
    for (int T = blockIdx.x; T < ntile; T += gridDim.x) {
        int base = T << 5;
        __syncthreads();
        for (int i = tid; i < 1024; i += 256) {
            int r = i >> 5, c4 = i & 31;
            int m = base + r;
            float4 v = make_float4(0.f, 0.f, 0.f, 0.f);
            if (m < M) v = reinterpret_cast<const float4*>(sf)[m * 32 + c4];
            reinterpret_cast<float4*>(&rows_s[r][0])[c4] = v;
        }
        __syncthreads();
        float a0 = 0.f, a1 = 0.f, a2 = 0.f, a3 = 0.f;
#pragma unroll
        for (int c2 = 0; c2 < 128; c2 += 4) {
            float w0 = w_s[c2 * 32 + c], w1 = w_s[(c2 + 1) * 32 + c];
            float w2 = w_s[(c2 + 2) * 32 + c], w3 = w_s[(c2 + 3) * 32 + c];
            float4 r0 = reinterpret_cast<const float4*>(&rows_s[rq][0])[c2 >> 2];
            float4 r1 = reinterpret_cast<const float4*>(&rows_s[rq + 8][0])[c2 >> 2];
            float4 r2 = reinterpret_cast<const float4*>(&rows_s[rq + 16][0])[c2 >> 2];
            float4 r3 = reinterpret_cast<const float4*>(&rows_s[rq + 24][0])[c2 >> 2];
            a0 = fmaf(r0.x, w0, a0); a0 = fmaf(r0.y, w1, a0); a0 = fmaf(r0.z, w2, a0); a0 = fmaf(r0.w, w3, a0);
            a1 = fmaf(r1.x, w0, a1); a1 = fmaf(r1.y, w1, a1); a1 = fmaf(r1.z, w2, a1); a1 = fmaf(r1.w, w3, a1);
            a2 = fmaf(r2.x, w0, a2); a2 = fmaf(r2.y, w1, a2); a2 = fmaf(r2.z, w2, a2); a2 = fmaf(r2.w, w3, a2);
            a3 = fmaf(r3.x, w0, a3); a3 = fmaf(r3.y, w1, a3); a3 = fmaf(r3.z, w2, a3); a3 = fmaf(r3.w, w3, a3);
        }
        int m;
        m = base + rq;      if (m < M) { g_y1[m * 32 + c] = a0; fsum += a0; fsq += a0 * a0; }
        m = base + rq + 8;  if (m < M) { g_y1[m * 32 + c] = a1; fsum += a1; fsq += a1 * a1; }
        m = base + rq + 16; if (m < M) { g_y1[m * 32 + c] = a2; fsum += a2; fsq += a2 * a2; }
        m = base + rq + 24; if (m < M) { g_y1[m * 32 + c] = a3; fsum += a3; fsq += a3 * a3; }
    }
    __syncthreads();
    red_s[rq][c] = fsum; __syncthreads();
    if (rq == 0) {
        float s = 0.f;
#pragma unroll
        for (int i = 0; i < 8; i++) s += red_s[i][c];
        atomicAdd(&g_acc[c], (double)s);
    }
    __syncthreads();
    red_s[rq][c] = fsq; __syncthreads();
    if (rq == 0) {
        float s = 0.f;
#pragma unroll
        for (int i = 0; i < 8; i++) s += red_s[i][c];
        atomicAdd(&g_acc[32 + c], (double)s);
    }
}

// ---------------- finalize: a = g/sqrt(var+eps), c = b - mean*a ----------------
__global__ void kpi_finalize_kernel(int stage, const float* __restrict__ g,
                                    const float* __restrict__ b, double invM) {
    int t = threadIdx.x;
    const double* sum; const double* sq; float* a; float* cc; int n;
    if (stage == 0)      { sum = g_acc;       sq = g_acc + 32;  a = g_a1; cc = g_c1; n = 32; }
    else if (stage == 1) { sum = g_acc + 64;  sq = g_acc + 96;  a = g_aC; cc = g_cC; n = 32; }
    else                 { sum = g_acc + 128; sq = g_acc + 256; a = g_a3; cc = g_c3; n = 128; }
    if (t < n) {
        double mean = sum[t] * invM;
        double var  = sq[t] * invM - mean * mean;
        float inv = (float)(1.0 / sqrt(var + 1e-5));
        float av = g[t] * inv;
        a[t]  = av;
        cc[t] = b[t] - (float)mean * av;
    }
}

// ---------------- K3: KPInv conv (warp per point), fused bn+lrelu on gather ----------------
__global__ void __launch_bounds__(256, 4) kpi_conv_kernel(const float* __restrict__ qp,
                                                          const float* __restrict__ sp,
                                                          const int* __restrict__ nidx,
                                                          const float* __restrict__ kp,
                                                          const float* __restrict__ wg1,
                                                          const float* __restrict__ bg1,
                                                          const float* __restrict__ wg2,
                                                          const float* __restrict__ bg2, int M) {
    __shared__ __align__(16) float nfeat_s[8][32][32]; // 32 KB
    __shared__ float omg_s[8][32][2];
    __shared__ float center_s[8][32];
    __shared__ float hid_s[8][8];
    __shared__ float wv_s[8][32];
    __shared__ float kp_s[16][4];     // x,y,z,|k|^2
    __shared__ float wg1_s[32][8];
    __shared__ float bg1_s[8];
    __shared__ float wg2_s[8][32];    // 30 used per row
    __shared__ float bg2_s[32];

    int tid = threadIdx.x, wid = tid >> 5, t = tid & 31;
    // load small params
    if (tid < 15) {
        float kx = kp[3 * tid], ky = kp[3 * tid + 1], kz = kp[3 * tid + 2];
        kp_s[tid][0] = kx; kp_s[tid][1] = ky; kp_s[tid][2] = kz;
        kp_s[tid][3] = kx * kx + ky * ky + kz * kz;
    }
    for (int i = tid; i < 256; i += 256) wg1_s[i >> 3][i & 7] = wg1[i];
    if (tid < 8) bg1_s[tid] = bg1[tid];
    if (tid < 240) wg2_s[tid / 30][tid % 30] = wg2[tid];
    if (tid < 30) bg2_s[tid] = bg2[tid];
    __syncthreads();

    // per-lane (channel) BN affine for unary1 output
    float a1t = g_a1[t], c1t = g_c1[t];

    float fsum = 0.f, fsq = 0.f;
    for (int m = blockIdx.x * 8 + wid; m < M; m += gridDim.x * 8) {
        int j = nidx[m * 32 + t];
        float qx = qp[3 * m], qy = qp[3 * m + 1], qz = qp[3 * m + 2];
        float nx = sp[3 * j] - qx, ny = sp[3 * j + 1] - qy, nz = sp[3 * j + 2] - qz;
        float nn = nx * nx + ny * ny + nz * nz;
        float infl[15];
#pragma unroll
        for (int k = 0; k < 15; k++) {
            float d2 = nn + kp_s[k][3]
                     - 2.f * (nx * kp_s[k][0] + ny * kp_s[k][1] + nz * kp_s[k][2]);
            infl[k] = fmaxf(1.f - sqrtf(fmaxf(d2, 0.f)), 0.f);
        }
        // gather neighbor features (apply unary1 BN + lrelu on the fly); lane t = channel t
        float cmax = -3.4e38f;
#pragma unroll
        for (int h = 0; h < 32; h++) {
            int jh = __shfl_sync(0xffffffffu, j, h);
            float v = lrelu(fmaf(g_y1[jh * 32 + t], a1t, c1t));
            nfeat_s[wid][h][t] = v;
            cmax = fmaxf(cmax, v);
        }
        center_s[wid][t] = cmax;
        __syncwarp();
        // hidden = lrelu(center @ w_g1 + b_g1), lanes 0..7
        if (t < 8) {
            float a = bg1_s[t];
#pragma unroll
            for (int c2 = 0; c2 < 32; c2++) a = fmaf(center_s[wid][c2], wg1_s[c2][t], a);
            hid_s[wid][t] = lrelu(a);
        }
        __syncwarp();
        // w = hidden @ w_g2 + b_g2, lanes 0..29  (w[k,g] = w[2k+g])
        if (t < 30) {
            float a = bg2_s[t];
#pragma unroll
            for (int k8 = 0; k8 < 8; k8++) a = fmaf(hid_s[wid][k8], wg2_s[k8][t], a);
            wv_s[wid][t] = a;
        }
        __syncwarp();
        // omega[h,g] = sum_k w[k,g] * infl[h,k], lane t = neighbor h
        float om0 = 0.f, om1 = 0.f;
#pragma unroll
        for (int k = 0; k < 15; k++) {
            om0 = fmaf(wv_s[wid][2 * k], infl[k], om0);
            om1 = fmaf(wv_s[wid][2 * k + 1], infl[k], om1);
        }
        omg_s[wid][t][0] = om0;
        omg_s[wid][t][1] = om1;
        __syncwarp();
        // out[c] = sum_h omega[h, c>>4] * nfeat[h,c], lane t = channel c
        int grp = t >> 4;
        float out = 0.f;
#pragma unroll
        for (int h = 0; h < 32; h++) out = fmaf(omg_s[wid][h][grp], nfeat_s[wid][h][t], out);
        g_y2[m * 32 + t] = out;
        fsum += out; fsq += out * out;
        __syncwarp();
    }
    // block-reduce column stats (column == lane id)
    __syncthreads();
    center_s[wid][t] = fsum; __syncthreads();
    if (wid == 0) {
        float s = 0.f;
#pragma unroll
        for (int i = 0; i < 8; i++) s += center_s[i][t];
        atomicAdd(&g_acc[64 + t], (double)s);
    }
    __syncthreads();
    center_s[wid][t] = fsq; __syncthreads();
    if (wid == 0) {
        float s = 0.f;
#pragma unroll
        for (int i = 0; i < 8; i++) s += center_s[i][t];
        atomicAdd(&g_acc[96 + t], (double)s);
    }
}

// ---------------- K5: z = lrelu(bn(y2)) @ w_u2  (M,32)x(32,128), + column stats ----------------
__global__ void __launch_bounds__(256) kpi_u2_kernel(const float* __restrict__ w, int M) {
    __shared__ __align__(16) float w_s[4096];     // [c2][j] 32x128
    __shared__ __align__(16) float xs[8][32];
    __shared__ float red_s[2][128];
    int tid = threadIdx.x;
    for (int i = tid; i < 4096; i += 256) w_s[i] = w[i];
    int j = tid & 127, rr = tid >> 7;
    float fsum = 0.f, fsq = 0.f;
    int ntile = (M + 7) >> 3;
    for (int T = blockIdx.x; T < ntile; T += gridDim.x) {
        int base = T << 3;
        __syncthreads();
        {
            int r = tid >> 5, cc = tid & 31;
            int m = base + r;
            float v = 0.f;
            if (m < M) {
                v = g_y2[m * 32 + cc];
                v = lrelu(fmaf(v, g_aC[cc], g_cC[cc]));
            }
            xs[r][cc] = v;
        }
        __syncthreads();
        float a0 = 0.f, a1 = 0.f, a2 = 0.f, a3 = 0.f;
#pragma unroll
        for (int c2 = 0; c2 < 32; c2 += 4) {
            float4 x0 = reinterpret_cast<const float4*>(&xs[rr][0])[c2 >> 2];
            float4 x1 = reinterpret_cast<const float4*>(&xs[rr + 2][0])[c2 >> 2];
            float4 x2 = reinterpret_cast<const float4*>(&xs[rr + 4][0])[c2 >> 2];
            float4 x3 = reinterpret_cast<const float4*>(&xs[rr + 6][0])[c2 >> 2];
            float w0 = w_s[c2 * 128 + j], w1 = w_s[(c2 + 1) * 128 + j];
            float w2 = w_s[(c2 + 2) * 128 + j], w3 = w_s[(c2 + 3) * 128 + j];
            a0 = fmaf(x0.x, w0, a0); a0 = fmaf(x0.y, w1, a0); a0 = fmaf(x0.z, w2, a0); a0 = fmaf(x0.w, w3, a0);
            a1 = fmaf(x1.x, w0, a1); a1 = fmaf(x1.y, w1, a1); a1 = fmaf(x1.z, w2, a1); a1 = fmaf(x1.w, w3, a1);
            a2 = fmaf(x2.x, w0, a2); a2 = fmaf(x2.y, w1, a2); a2 = fmaf(x2.z, w2, a2); a2 = fmaf(x2.w, w3, a2);
            a3 = fmaf(x3.x, w0, a3); a3 = fmaf(x3.y, w1, a3); a3 = fmaf(x3.z, w2, a3); a3 = fmaf(x3.w, w3, a3);
        }
        int m;
        m = base + rr;     if (m < M) { g_z[m * 128 + j] = a0; fsum += a0; fsq += a0 * a0; }
        m = base + rr + 2; if (m < M) { g_z[m * 128 + j] = a1; fsum += a1; fsq += a1 * a1; }
        m = base + rr + 4; if (m < M) { g_z[m * 128 + j] = a2; fsum += a2; fsq += a2 * a2; }
        m = base + rr + 6; if (m < M) { g_z[m * 128 + j] = a3; fsum += a3; fsq += a3 * a3; }
    }
    __syncthreads();
    red_s[rr][j] = fsum; __syncthreads();
    if (rr == 0) atomicAdd(&g_acc[128 + j], (double)(red_s[0][j] + red_s[1][j]));
    __syncthreads();
    red_s[rr][j] = fsq; __syncthreads();
    if (rr == 0) atomicAdd(&g_acc[256 + j], (double)(red_s[0][j] + red_s[1][j]));
}

// ---------------- K7: out = lrelu(bn(z) + s_feats) ----------------
__global__ void kpi_final_kernel(const float* __restrict__ sf, float* __restrict__ out, int n4) {
    int i = blockIdx.x * blockDim.x + threadIdx.x;
    int stride = gridDim.x * blockDim.x;
    for (; i < n4; i += stride) {
        float4 z = reinterpret_cast<const float4*>(g_z)[i];
        float4 s = reinterpret_cast<const float4*>(sf)[i];
        int c = (i << 2) & 127;
        float4 r;
        r.x = lrelu(fmaf(z.x, g_a3[c + 0], g_c3[c + 0]) + s.x);
        r.y = lrelu(fmaf(z.y, g_a3[c + 1], g_c3[c + 1]) + s.y);
        r.z = lrelu(fmaf(z.z, g_a3[c + 2], g_c3[c + 2]) + s.z);
        r.w = lrelu(fmaf(z.w, g_a3[c + 3], g_c3[c + 3]) + s.w);
        reinterpret_cast<float4*>(out)[i] = r;
    }
}

// ---------------- launch ----------------
extern "C" void kernel_launch(void* const* d_in, const int* in_sizes, int n_in,
                              void* d_out, int out_size) {
    const float* q_pts   = (const float*)d_in[0];
    const float* s_pts   = (const float*)d_in[1];
    const float* s_feats = (const float*)d_in[2];
    const int*   nidx    = (const int*)d_in[3];
    const float* kp      = (const float*)d_in[4];
    const float* w_u1    = (const float*)d_in[5];
    const float* g_u1    = (const float*)d_in[6];
    const float* b_u1    = (const float*)d_in[7];
    const float* w_g1    = (const float*)d_in[8];
    const float* b_g1    = (const float*)d_in[9];
    const float* w_g2    = (const float*)d_in[10];
    const float* b_g2    = (const float*)d_in[11];
    const float* g_c     = (const float*)d_in[12];
    const float* b_c     = (const float*)d_in[13];
    const float* w_u2    = (const float*)d_in[14];
    const float* g_u2    = (const float*)d_in[15];
    const float* b_u2    = (const float*)d_in[16];
    float* out = (float*)d_out;

    int M = in_sizes[0] / 3;
    double invM = 1.0 / (double)M;

    kpi_zero_kernel<<<1, 384>>>();
    kpi_u1_kernel<<<NBLK, 256>>>(s_feats, w_u1, M);
    kpi_finalize_kernel<<<1, 128>>>(0, g_u1, b_u1, invM);
    kpi_conv_kernel<<<NBLK, 256>>>(q_pts, s_pts, nidx, kp, w_g1, b_g1, w_g2, b_g2, M);
    kpi_finalize_kernel<<<1, 128>>>(1, g_c, b_c, invM);
    kpi_u2_kernel<<<NBLK, 256>>>(w_u2, M);
    kpi_finalize_kernel<<<1, 128>>>(2, g_u2, b_u2, invM);
    kpi_final_kernel<<<1184, 256>>>(s_feats, out, M * 32);
}

// round 4
// speedup vs baseline: 1.1991x; 1.0579x over previous
#include <cuda_runtime.h>

#define MAXPTS 50000
#define NBLK 592
#define CONVBLK 444

// ---------------- scratch (no allocation allowed) ----------------
__device__ float  g_y1[MAXPTS * 32];    // unary1 pre-BN
__device__ float  g_y2[MAXPTS * 32];    // conv output pre-BN
__device__ float  g_z[MAXPTS * 128];    // unary2 pre-BN
__device__ double g_acc[384];           // [0:32) sum1 [32:64) sq1 [64:96) sumC [96:128) sqC [128:256) sum3 [256:384) sq3
__device__ float  g_a1[32], g_c1[32], g_aC[32], g_cC[32], g_a3[128], g_c3[128];

__device__ __forceinline__ float lrelu(float x) { return fmaxf(x, 0.1f * x); }

// ---------------- K0: zero accumulators ----------------
__global__ void kpi_zero_kernel() {
    int t = threadIdx.x;
    if (t < 384) g_acc[t] = 0.0;
}

// ---------------- K1: y1 = s_feats @ w_u1  (M,128)x(128,32), + column stats ----------------
__global__ void __launch_bounds__(256) kpi_u1_kernel(const float* __restrict__ sf,
                                                     const float* __restrict__ w, int M) {
    __shared__ __align__(16) float w_s[4096];        // [c2][c] 128x32
    __shared__ __align__(16) float rows_s[32][128];
    __shared__ float red_s[8][32];
    int tid = threadIdx.x;
    for (int i = tid; i < 4096; i += 256) w_s[i] = w[i];
    int c = tid & 31, rq = tid >> 5;
    float fsum = 0.f, fsq = 0.f;
    int ntile = (M + 31) >> 5;
    for (int T = blockIdx.x; T < ntile; T += gridDim.x) {
        int base = T << 5;
        __syncthreads();
        for (int i = tid; i < 1024; i += 256) {
            int r = i >> 5, c4 = i & 31;
            int m = base + r;
            float4 v = make_float4(0.f, 0.f, 0.f, 0.f);
            if (m < M) v = reinterpret_cast<const float4*>(sf)[m * 32 + c4];
            reinterpret_cast<float4*>(&rows_s[r][0])[c4] = v;
        }
        __syncthreads();
        float a0 = 0.f, a1 = 0.f, a2 = 0.f, a3 = 0.f;
#pragma unroll
        for (int c2 = 0; c2 < 128; c2 += 4) {
            float w0 = w_s[c2 * 32 + c], w1 = w_s[(c2 + 1) * 32 + c];
            float w2 = w_s[(c2 + 2) * 32 + c], w3 = w_s[(c2 + 3) * 32 + c];
            float4 r0 = reinterpret_cast<const float4*>(&rows_s[rq][0])[c2 >> 2];
            float4 r1 = reinterpret_cast<const float4*>(&rows_s[rq + 8][0])[c2 >> 2];
            float4 r2 = reinterpret_cast<const float4*>(&rows_s[rq + 16][0])[c2 >> 2];
            float4 r3 = reinterpret_cast<const float4*>(&rows_s[rq + 24][0])[c2 >> 2];
            a0 = fmaf(r0.x, w0, a0); a0 = fmaf(r0.y, w1, a0); a0 = fmaf(r0.z, w2, a0); a0 = fmaf(r0.w, w3, a0);
            a1 = fmaf(r1.x, w0, a1); a1 = fmaf(r1.y, w1, a1); a1 = fmaf(r1.z, w2, a1); a1 = fmaf(r1.w, w3, a1);
            a2 = fmaf(r2.x, w0, a2); a2 = fmaf(r2.y, w1, a2); a2 = fmaf(r2.z, w2, a2); a2 = fmaf(r2.w, w3, a2);
            a3 = fmaf(r3.x, w0, a3); a3 = fmaf(r3.y, w1, a3); a3 = fmaf(r3.z, w2, a3); a3 = fmaf(r3.w, w3, a3);
        }
        int m;
        m = base + rq;      if (m < M) { g_y1[m * 32 + c] = a0; fsum += a0; fsq += a0 * a0; }
        m = base + rq + 8;  if (m < M) { g_y1[m * 32 + c] = a1; fsum += a1; fsq += a1 * a1; }
        m = base + rq + 16; if (m < M) { g_y1[m * 32 + c] = a2; fsum += a2; fsq += a2 * a2; }
        m = base + rq + 24; if (m < M) { g_y1[m * 32 + c] = a3; fsum += a3; fsq += a3 * a3; }
    }
    __syncthreads();
    red_s[rq][c] = fsum; __syncthreads();
    if (rq == 0) {
        float s = 0.f;
#pragma unroll
        for (int i = 0; i < 8; i++) s += red_s[i][c];
        atomicAdd(&g_acc[c], (double)s);
    }
    __syncthreads();
    red_s[rq][c] = fsq; __syncthreads();
    if (rq == 0) {
        float s = 0.f;
#pragma unroll
        for (int i = 0; i < 8; i++) s += red_s[i][c];
        atomicAdd(&g_acc[32 + c], (double)s);
    }
}

// ---------------- finalize: a = g/sqrt(var+eps), c = b - mean*a ----------------
__global__ void kpi_finalize_kernel(int stage, const float* __restrict__ g,
                                    const float* __restrict__ b, double invM) {
    int t = threadIdx.x;
    const double* sum; const double* sq; float* a; float* cc; int n;
    if (stage == 0)      { sum = g_acc;       sq = g_acc + 32;  a = g_a1; cc = g_c1; n = 32; }
    else if (stage == 1) { sum = g_acc + 64;  sq = g_acc + 96;  a = g_aC; cc = g_cC; n = 32; }
    else                 { sum = g_acc + 128; sq = g_acc + 256; a = g_a3; cc = g_c3; n = 128; }
    if (t < n) {
        double mean = sum[t] * invM;
        double var  = sq[t] * invM - mean * mean;
        float inv = (float)(1.0 / sqrt(var + 1e-5));
        float av = g[t] * inv;
        a[t]  = av;
        cc[t] = b[t] - (float)mean * av;
    }
}

// ---------------- K3: KPInv conv (warp per point), nfeat in registers ----------------
__global__ void __launch_bounds__(256, 3) kpi_conv_kernel(const float* __restrict__ qp,
                                                          const float* __restrict__ sp,
                                                          const int* __restrict__ nidx,
                                                          const float* __restrict__ kp,
                                                          const float* __restrict__ wg1,
                                                          const float* __restrict__ bg1,
                                                          const float* __restrict__ wg2,
                                                          const float* __restrict__ bg2, int M) {
    __shared__ float omg_s[8][32][2];
    __shared__ float center_s[8][32];
    __shared__ float hid_s[8][8];
    __shared__ float wv_s[8][32];
    __shared__ __align__(16) float4 kp_s[15];   // x,y,z,|k|^2
    __shared__ float wg1_s[32][8];
    __shared__ float bg1_s[8];
    __shared__ float wg2_s[8][32];    // 30 used per row
    __shared__ float bg2_s[32];
    __shared__ float red_s[8][32];

    int tid = threadIdx.x, wid = tid >> 5, t = tid & 31;
    // load small params
    if (tid < 15) {
        float kx = kp[3 * tid], ky = kp[3 * tid + 1], kz = kp[3 * tid + 2];
        kp_s[tid] = make_float4(kx, ky, kz, kx * kx + ky * ky + kz * kz);
    }
    for (int i = tid; i < 256; i += 256) wg1_s[i >> 3][i & 7] = wg1[i];
    if (tid < 8) bg1_s[tid] = bg1[tid];
    if (tid < 240) wg2_s[tid / 30][tid % 30] = wg2[tid];
    if (tid < 30) bg2_s[tid] = bg2[tid];
    __syncthreads();

    // per-lane (channel) BN affine for unary1 output
    float a1t = g_a1[t], c1t = g_c1[t];

    float fsum = 0.f, fsq = 0.f;
    for (int m = blockIdx.x * 8 + wid; m < M; m += gridDim.x * 8) {
        int j = nidx[m * 32 + t];
        float qx = qp[3 * m], qy = qp[3 * m + 1], qz = qp[3 * m + 2];
        float nx = sp[3 * j] - qx, ny = sp[3 * j + 1] - qy, nz = sp[3 * j + 2] - qz;
        float nn = nx * nx + ny * ny + nz * nz;

        // gather neighbor features (apply unary1 BN + lrelu on the fly)
        // lane t = channel t; v[h] = feature of neighbor h at channel t
        float v[32];
        float cmax = -3.4e38f;
#pragma unroll
        for (int h = 0; h < 32; h++) {
            int jh = __shfl_sync(0xffffffffu, j, h);
            v[h] = lrelu(fmaf(g_y1[jh * 32 + t], a1t, c1t));
            cmax = fmaxf(cmax, v[h]);
        }
        center_s[wid][t] = cmax;
        __syncwarp();
        // hidden = lrelu(center @ w_g1 + b_g1), lanes 0..7
        if (t < 8) {
            float a = bg1_s[t];
#pragma unroll
            for (int c2 = 0; c2 < 32; c2++) a = fmaf(center_s[wid][c2], wg1_s[c2][t], a);
            hid_s[wid][t] = lrelu(a);
        }
        __syncwarp();
        // w = hidden @ w_g2 + b_g2, lanes 0..29  (w[k,g] = w[2k+g])
        if (t < 30) {
            float a = bg2_s[t];
#pragma unroll
            for (int k8 = 0; k8 < 8; k8++) a = fmaf(hid_s[wid][k8], wg2_s[k8][t], a);
            wv_s[wid][t] = a;
        }
        __syncwarp();
        // omega[h,g] = sum_k w[k,g] * infl[h,k]; lane t = neighbor h; infl fused
        float om0 = 0.f, om1 = 0.f;
#pragma unroll
        for (int k = 0; k < 15; k++) {
            float4 kk = kp_s[k];
            float d2 = nn + kk.w - 2.f * (nx * kk.x + ny * kk.y + nz * kk.z);
            float infl = fmaxf(1.f - sqrtf(fmaxf(d2, 0.f)), 0.f);
            om0 = fmaf(wv_s[wid][2 * k], infl, om0);
            om1 = fmaf(wv_s[wid][2 * k + 1], infl, om1);
        }
        omg_s[wid][t][0] = om0;
        omg_s[wid][t][1] = om1;
        __syncwarp();
        // out[c] = sum_h omega[h, c>>4] * v[h], lane t = channel c
        int grp = t >> 4;
        float out = 0.f;
#pragma unroll
        for (int h = 0; h < 32; h++) out = fmaf(omg_s[wid][h][grp], v[h], out);
        g_y2[m * 32 + t] = out;
        fsum += out; fsq += out * out;
        __syncwarp();
    }
    // block-reduce column stats (column == lane id)
    __syncthreads();
    red_s[wid][t] = fsum; __syncthreads();
    if (wid == 0) {
        float s = 0.f;
#pragma unroll
        for (int i = 0; i < 8; i++) s += red_s[i][t];
        atomicAdd(&g_acc[64 + t], (double)s);
    }
    __syncthreads();
    red_s[wid][t] = fsq; __syncthreads();
    if (wid == 0) {
        float s = 0.f;
#pragma unroll
        for (int i = 0; i < 8; i++) s += red_s[i][t];
        atomicAdd(&g_acc[96 + t], (double)s);
    }
}

// ---------------- K5: z = lrelu(bn(y2)) @ w_u2  (M,32)x(32,128), + column stats ----------------
__global__ void __launch_bounds__(256) kpi_u2_kernel(const float* __restrict__ w, int M) {
    __shared__ __align__(16) float w_s[4096];     // [c2][j] 32x128
    __shared__ __align__(16) float xs[8][32];
    __shared__ float red_s[2][128];
    int tid = threadIdx.x;
    for (int i = tid; i < 4096; i += 256) w_s[i] = w[i];
    int j = tid & 127, rr = tid >> 7;
    float fsum = 0.f, fsq = 0.f;
    int ntile = (M + 7) >> 3;
    for (int T = blockIdx.x; T < ntile; T += gridDim.x) {
        int base = T << 3;
        __syncthreads();
        {
            int r = tid >> 5, cc = tid & 31;
            int m = base + r;
            float v = 0.f;
            if (m < M) {
                v = g_y2[m * 32 + cc];
                v = lrelu(fmaf(v, g_aC[cc], g_cC[cc]));
            }
            xs[r][cc] = v;
        }
        __syncthreads();
        float a0 = 0.f, a1 = 0.f, a2 = 0.f, a3 = 0.f;
#pragma unroll
        for (int c2 = 0; c2 < 32; c2 += 4) {
            float4 x0 = reinterpret_cast<const float4*>(&xs[rr][0])[c2 >> 2];
            float4 x1 = reinterpret_cast<const float4*>(&xs[rr + 2][0])[c2 >> 2];
            float4 x2 = reinterpret_cast<const float4*>(&xs[rr + 4][0])[c2 >> 2];
            float4 x3 = reinterpret_cast<const float4*>(&xs[rr + 6][0])[c2 >> 2];
            float w0 = w_s[c2 * 128 + j], w1 = w_s[(c2 + 1) * 128 + j];
            float w2 = w_s[(c2 + 2) * 128 + j], w3 = w_s[(c2 + 3) * 128 + j];
            a0 = fmaf(x0.x, w0, a0); a0 = fmaf(x0.y, w1, a0); a0 = fmaf(x0.z, w2, a0); a0 = fmaf(x0.w, w3, a0);
            a1 = fmaf(x1.x, w0, a1); a1 = fmaf(x1.y, w1, a1); a1 = fmaf(x1.z, w2, a1); a1 = fmaf(x1.w, w3, a1);
            a2 = fmaf(x2.x, w0, a2); a2 = fmaf(x2.y, w1, a2); a2 = fmaf(x2.z, w2, a2); a2 = fmaf(x2.w, w3, a2);
            a3 = fmaf(x3.x, w0, a3); a3 = fmaf(x3.y, w1, a3); a3 = fmaf(x3.z, w2, a3); a3 = fmaf(x3.w, w3, a3);
        }
        int m;
        m = base + rr;     if (m < M) { g_z[m * 128 + j] = a0; fsum += a0; fsq += a0 * a0; }
        m = base + rr + 2; if (m < M) { g_z[m * 128 + j] = a1; fsum += a1; fsq += a1 * a1; }
        m = base + rr + 4; if (m < M) { g_z[m * 128 + j] = a2; fsum += a2; fsq += a2 * a2; }
        m = base + rr + 6; if (m < M) { g_z[m * 128 + j] = a3; fsum += a3; fsq += a3 * a3; }
    }
    __syncthreads();
    red_s[rr][j] = fsum; __syncthreads();
    if (rr == 0) atomicAdd(&g_acc[128 + j], (double)(red_s[0][j] + red_s[1][j]));
    __syncthreads();
    red_s[rr][j] = fsq; __syncthreads();
    if (rr == 0) atomicAdd(&g_acc[256 + j], (double)(red_s[0][j] + red_s[1][j]));
}

// ---------------- K7: out = lrelu(bn(z) + s_feats) ----------------
__global__ void kpi_final_kernel(const float* __restrict__ sf, float* __restrict__ out, int n4) {
    int i = blockIdx.x * blockDim.x + threadIdx.x;
    int stride = gridDim.x * blockDim.x;
    for (; i < n4; i += stride) {
        float4 z = reinterpret_cast<const float4*>(g_z)[i];
        float4 s = reinterpret_cast<const float4*>(sf)[i];
        int c = (i << 2) & 127;
        float4 r;
        r.x = lrelu(fmaf(z.x, g_a3[c + 0], g_c3[c + 0]) + s.x);
        r.y = lrelu(fmaf(z.y, g_a3[c + 1], g_c3[c + 1]) + s.y);
        r.z = lrelu(fmaf(z.z, g_a3[c + 2], g_c3[c + 2]) + s.z);
        r.w = lrelu(fmaf(z.w, g_a3[c + 3], g_c3[c + 3]) + s.w);
        reinterpret_cast<float4*>(out)[i] = r;
    }
}

// ---------------- launch ----------------
extern "C" void kernel_launch(void* const* d_in, const int* in_sizes, int n_in,
                              void* d_out, int out_size) {
    const float* q_pts   = (const float*)d_in[0];
    const float* s_pts   = (const float*)d_in[1];
    const float* s_feats = (const float*)d_in[2];
    const int*   nidx    = (const int*)d_in[3];
    const float* kp      = (const float*)d_in[4];
    const float* w_u1    = (const float*)d_in[5];
    const float* g_u1    = (const float*)d_in[6];
    const float* b_u1    = (const float*)d_in[7];
    const float* w_g1    = (const float*)d_in[8];
    const float* b_g1    = (const float*)d_in[9];
    const float* w_g2    = (const float*)d_in[10];
    const float* b_g2    = (const float*)d_in[11];
    const float* g_c     = (const float*)d_in[12];
    const float* b_c     = (const float*)d_in[13];
    const float* w_u2    = (const float*)d_in[14];
    const float* g_u2    = (const float*)d_in[15];
    const float* b_u2    = (const float*)d_in[16];
    float* out = (float*)d_out;

    int M = in_sizes[0] / 3;
    double invM = 1.0 / (double)M;

    kpi_zero_kernel<<<1, 384>>>();
    kpi_u1_kernel<<<NBLK, 256>>>(s_feats, w_u1, M);
    kpi_finalize_kernel<<<1, 128>>>(0, g_u1, b_u1, invM);
    kpi_conv_kernel<<<CONVBLK, 256>>>(q_pts, s_pts, nidx, kp, w_g1, b_g1, w_g2, b_g2, M);
    kpi_finalize_kernel<<<1, 128>>>(1, g_c, b_c, invM);
    kpi_u2_kernel<<<NBLK, 256>>>(w_u2, M);
    kpi_finalize_kernel<<<1, 128>>>(2, g_u2, b_u2, invM);
    kpi_final_kernel<<<1184, 256>>>(s_feats, out, M * 32);
}

// round 8
// speedup vs baseline: 1.2930x; 1.0783x over previous
#include <cuda_runtime.h>

#define MAXPTS 50000
#define NBLK 592
#define CONVBLK 444

// ---------------- scratch (no allocation allowed) ----------------
__device__ __align__(16) float  g_y1[MAXPTS * 32];    // unary1 pre-BN
__device__ __align__(16) float  g_y2[MAXPTS * 32];    // conv output pre-BN
__device__ __align__(16) float  g_z[MAXPTS * 128];    // unary2 pre-BN
__device__ double g_acc[384];           // [0:32) sum1 [32:64) sq1 [64:96) sumC [96:128) sqC [128:256) sum3 [256:384) sq3
__device__ __align__(16) float g_a1[32];
__device__ __align__(16) float g_c1[32];
__device__ __align__(16) float g_aC[32];
__device__ __align__(16) float g_cC[32];
__device__ __align__(16) float g_a3[128];
__device__ __align__(16) float g_c3[128];

__device__ __forceinline__ float lrelu(float x) { return fmaxf(x, 0.1f * x); }

// ---------------- K1: y1 = s_feats @ w_u1  (M,128)x(128,32), + column stats ----------------
__global__ void __launch_bounds__(256) kpi_u1_kernel(const float* __restrict__ sf,
                                                     const float* __restrict__ w, int M) {
    __shared__ __align__(16) float w_s[4096];        // [c2][c] 128x32
    __shared__ __align__(16) float rows_s[32][128];
    __shared__ float red_s[8][32];
    int tid = threadIdx.x;
    for (int i = tid; i < 4096; i += 256) w_s[i] = w[i];
    int c = tid & 31, rq = tid >> 5;
    float fsum = 0.f, fsq = 0.f;
    int ntile = (M + 31) >> 5;
    for (int T = blockIdx.x; T < ntile; T += gridDim.x) {
        int base = T << 5;
        __syncthreads();
        for (int i = tid; i < 1024; i += 256) {
            int r = i >> 5, c4 = i & 31;
            int m = base + r;
            float4 v = make_float4(0.f, 0.f, 0.f, 0.f);
            if (m < M) v = reinterpret_cast<const float4*>(sf)[m * 32 + c4];
            reinterpret_cast<float4*>(&rows_s[r][0])[c4] = v;
        }
        __syncthreads();
        float a0 = 0.f, a1 = 0.f, a2 = 0.f, a3 = 0.f;
#pragma unroll
        for (int c2 = 0; c2 < 128; c2 += 4) {
            float w0 = w_s[c2 * 32 + c], w1 = w_s[(c2 + 1) * 32 + c];
            float w2 = w_s[(c2 + 2) * 32 + c], w3 = w_s[(c2 + 3) * 32 + c];
            float4 r0 = reinterpret_cast<const float4*>(&rows_s[rq][0])[c2 >> 2];
            float4 r1 = reinterpret_cast<const float4*>(&rows_s[rq + 8][0])[c2 >> 2];
            float4 r2 = reinterpret_cast<const float4*>(&rows_s[rq + 16][0])[c2 >> 2];
            float4 r3 = reinterpret_cast<const float4*>(&rows_s[rq + 24][0])[c2 >> 2];
            a0 = fmaf(r0.x, w0, a0); a0 = fmaf(r0.y, w1, a0); a0 = fmaf(r0.z, w2, a0); a0 = fmaf(r0.w, w3, a0);
            a1 = fmaf(r1.x, w0, a1); a1 = fmaf(r1.y, w1, a1); a1 = fmaf(r1.z, w2, a1); a1 = fmaf(r1.w, w3, a1);
            a2 = fmaf(r2.x, w0, a2); a2 = fmaf(r2.y, w1, a2); a2 = fmaf(r2.z, w2, a2); a2 = fmaf(r2.w, w3, a2);
            a3 = fmaf(r3.x, w0, a3); a3 = fmaf(r3.y, w1, a3); a3 = fmaf(r3.z, w2, a3); a3 = fmaf(r3.w, w3, a3);
        }
        int m;
        m = base + rq;      if (m < M) { g_y1[m * 32 + c] = a0; fsum += a0; fsq += a0 * a0; }
        m = base + rq + 8;  if (m < M) { g_y1[m * 32 + c] = a1; fsum += a1; fsq += a1 * a1; }
        m = base + rq + 16; if (m < M) { g_y1[m * 32 + c] = a2; fsum += a2; fsq += a2 * a2; }
        m = base + rq + 24; if (m < M) { g_y1[m * 32 + c] = a3; fsum += a3; fsq += a3 * a3; }
    }
    __syncthreads();
    red_s[rq][c] = fsum; __syncthreads();
    if (rq == 0) {
        float s = 0.f;
#pragma unroll
        for (int i = 0; i < 8; i++) s += red_s[i][c];
        atomicAdd(&g_acc[c], (double)s);
    }
    __syncthreads();
    red_s[rq][c] = fsq; __syncthreads();
    if (rq == 0) {
        float s = 0.f;
#pragma unroll
        for (int i = 0; i < 8; i++) s += red_s[i][c];
        atomicAdd(&g_acc[32 + c], (double)s);
    }
}

// ---------------- finalize: a = g/sqrt(var+eps), c = b - mean*a; resets its acc slots ----------------
__global__ void kpi_finalize_kernel(int stage, const float* __restrict__ g,
                                    const float* __restrict__ b, double invM) {
    int t = threadIdx.x;
    double* sum; double* sq; float* a; float* cc; int n;
    if (stage == 0)      { sum = g_acc;       sq = g_acc + 32;  a = g_a1; cc = g_c1; n = 32; }
    else if (stage == 1) { sum = g_acc + 64;  sq = g_acc + 96;  a = g_aC; cc = g_cC; n = 32; }
    else                 { sum = g_acc + 128; sq = g_acc + 256; a = g_a3; cc = g_c3; n = 128; }
    if (t < n) {
        double mean = sum[t] * invM;
        double var  = sq[t] * invM - mean * mean;
        float inv = (float)(1.0 / sqrt(var + 1e-5));
        float av = g[t] * inv;
        a[t]  = av;
        cc[t] = b[t] - (float)mean * av;
        // reset for next graph replay (module init covers the first call)
        sum[t] = 0.0;
        sq[t]  = 0.0;
    }
}

// ---------------- K3: KPInv conv (warp per point), float4 gather, butterfly reductions ----------------
__global__ void __launch_bounds__(256, 3) kpi_conv_kernel(const float* __restrict__ qp,
                                                          const float* __restrict__ sp,
                                                          const int* __restrict__ nidx,
                                                          const float* __restrict__ kp,
                                                          const float* __restrict__ wg1,
                                                          const float* __restrict__ bg1,
                                                          const float* __restrict__ wg2,
                                                          const float* __restrict__ bg2, int M) {
    __shared__ __align__(16) float omg_s[8][32][2];
    __shared__ __align__(16) float center_s[8][32];
    __shared__ float hid_s[8][8];
    __shared__ float wv_s[8][32];
    __shared__ __align__(16) float4 kp_s[15];   // x,y,z,|k|^2
    __shared__ float wg1_s[32][8];
    __shared__ float bg1_s[8];
    __shared__ float wg2_s[8][32];    // 30 used per row
    __shared__ float bg2_s[32];
    __shared__ __align__(16) float red_s[8][32];

    const unsigned FULL = 0xffffffffu;
    int tid = threadIdx.x, wid = tid >> 5, t = tid & 31;
    int r = t >> 3, q = t & 7;        // lane = r*8 + q
    // load small params
    if (tid < 15) {
        float kx = kp[3 * tid], ky = kp[3 * tid + 1], kz = kp[3 * tid + 2];
        kp_s[tid] = make_float4(kx, ky, kz, kx * kx + ky * ky + kz * kz);
    }
    for (int i = tid; i < 256; i += 256) wg1_s[i >> 3][i & 7] = wg1[i];
    if (tid < 8) bg1_s[tid] = bg1[tid];
    if (tid < 240) wg2_s[tid / 30][tid % 30] = wg2[tid];
    if (tid < 30) bg2_s[tid] = bg2[tid];
    __syncthreads();

    // per-lane BN affine for channels 4q..4q+3
    float4 a1q = reinterpret_cast<const float4*>(g_a1)[q];
    float4 c1q = reinterpret_cast<const float4*>(g_c1)[q];
    const float4* gy4 = reinterpret_cast<const float4*>(g_y1);

    int stride = gridDim.x * 8;
    int m = blockIdx.x * 8 + wid;
    // initial prefetch (every warp has at least one point: 3552 <= M)
    int j = nidx[m * 32 + t];
    float qx = qp[3 * m], qy = qp[3 * m + 1], qz = qp[3 * m + 2];

    float4 fsum4 = make_float4(0.f, 0.f, 0.f, 0.f);
    float4 fsq4  = make_float4(0.f, 0.f, 0.f, 0.f);

    for (; m < M; m += stride) {
        // positions: lane = neighbor h
        float nx = sp[3 * j] - qx, ny = sp[3 * j + 1] - qy, nz = sp[3 * j + 2] - qz;
        float nn = nx * nx + ny * ny + nz * nz;

        // prefetch next point's indices / query position
        int mn = m + stride;
        int jn = 0; float qxn = 0.f, qyn = 0.f, qzn = 0.f;
        if (mn < M) {
            jn = nidx[mn * 32 + t];
            qxn = qp[3 * mn]; qyn = qp[3 * mn + 1]; qzn = qp[3 * mn + 2];
        }

        // gather: iteration i loads row h = 4*i + r, channels 4q..4q+3 (LDG.128)
        float4 v4[8];
        float4 cmax4 = make_float4(-3.4e38f, -3.4e38f, -3.4e38f, -3.4e38f);
#pragma unroll
        for (int i = 0; i < 8; i++) {
            int jh = __shfl_sync(FULL, j, 4 * i + r);
            float4 raw = gy4[jh * 8 + q];
            float4 vv;
            vv.x = lrelu(fmaf(raw.x, a1q.x, c1q.x));
            vv.y = lrelu(fmaf(raw.y, a1q.y, c1q.y));
            vv.z = lrelu(fmaf(raw.z, a1q.z, c1q.z));
            vv.w = lrelu(fmaf(raw.w, a1q.w, c1q.w));
            v4[i] = vv;
            cmax4.x = fmaxf(cmax4.x, vv.x); cmax4.y = fmaxf(cmax4.y, vv.y);
            cmax4.z = fmaxf(cmax4.z, vv.z); cmax4.w = fmaxf(cmax4.w, vv.w);
        }
        // butterfly max across r (bits 3,4 of lane id)
#pragma unroll
        for (int ofs = 8; ofs <= 16; ofs <<= 1) {
            cmax4.x = fmaxf(cmax4.x, __shfl_xor_sync(FULL, cmax4.x, ofs));
            cmax4.y = fmaxf(cmax4.y, __shfl_xor_sync(FULL, cmax4.y, ofs));
            cmax4.z = fmaxf(cmax4.z, __shfl_xor_sync(FULL, cmax4.z, ofs));
            cmax4.w = fmaxf(cmax4.w, __shfl_xor_sync(FULL, cmax4.w, ofs));
        }
        if (r == 0) reinterpret_cast<float4*>(&center_s[wid][0])[q] = cmax4;
        __syncwarp();

        // hidden[q] = lrelu(b1[q] + sum_c center[c]*wg1[c][q]); split channel range over r
        {
            float a = 0.f;
#pragma unroll
            for (int e = 0; e < 8; e++)
                a = fmaf(center_s[wid][r * 8 + e], wg1_s[r * 8 + e][q], a);
            a += __shfl_xor_sync(FULL, a, 8);
            a += __shfl_xor_sync(FULL, a, 16);
            if (t < 8) hid_s[wid][t] = lrelu(a + bg1_s[t]);
        }
        __syncwarp();
        // w = hidden @ w_g2 + b_g2, lanes 0..29  (w[k,g] = w[2k+g])
        if (t < 30) {
            float a = bg2_s[t];
#pragma unroll
            for (int k8 = 0; k8 < 8; k8++) a = fmaf(hid_s[wid][k8], wg2_s[k8][t], a);
            wv_s[wid][t] = a;
        }
        __syncwarp();
        // omega[h,g] = sum_k w[k,g] * infl[h,k]; lane = neighbor h; infl fused
        float om0 = 0.f, om1 = 0.f;
#pragma unroll
        for (int k = 0; k < 15; k++) {
            float4 kk = kp_s[k];
            float d2 = nn + kk.w - 2.f * (nx * kk.x + ny * kk.y + nz * kk.z);
            float infl = fmaxf(1.f - sqrtf(fmaxf(d2, 0.f)), 0.f);
            om0 = fmaf(wv_s[wid][2 * k], infl, om0);
            om1 = fmaf(wv_s[wid][2 * k + 1], infl, om1);
        }
        omg_s[wid][t][0] = om0;
        omg_s[wid][t][1] = om1;
        __syncwarp();
        // out[4q+e] = sum_h omega[h, g] * v[h][4q+e]; g = q>>2; rows h = 4i+r
        int g = q >> 2;
        float4 o4 = make_float4(0.f, 0.f, 0.f, 0.f);
#pragma unroll
        for (int i = 0; i < 8; i++) {
            float w = omg_s[wid][4 * i + r][g];
            o4.x = fmaf(w, v4[i].x, o4.x);
            o4.y = fmaf(w, v4[i].y, o4.y);
            o4.z = fmaf(w, v4[i].z, o4.z);
            o4.w = fmaf(w, v4[i].w, o4.w);
        }
#pragma unroll
        for (int ofs = 8; ofs <= 16; ofs <<= 1) {
            o4.x += __shfl_xor_sync(FULL, o4.x, ofs);
            o4.y += __shfl_xor_sync(FULL, o4.y, ofs);
            o4.z += __shfl_xor_sync(FULL, o4.z, ofs);
            o4.w += __shfl_xor_sync(FULL, o4.w, ofs);
        }
        if (r == 0) {
            reinterpret_cast<float4*>(g_y2 + m * 32)[q] = o4;
            fsum4.x += o4.x; fsum4.y += o4.y; fsum4.z += o4.z; fsum4.w += o4.w;
            fsq4.x = fmaf(o4.x, o4.x, fsq4.x); fsq4.y = fmaf(o4.y, o4.y, fsq4.y);
            fsq4.z = fmaf(o4.z, o4.z, fsq4.z); fsq4.w = fmaf(o4.w, o4.w, fsq4.w);
        }
        j = jn; qx = qxn; qy = qyn; qz = qzn;
    }
    // block-reduce column stats (channels 4q+e live in lanes r==0)
    __syncthreads();
    if (r == 0) reinterpret_cast<float4*>(&red_s[wid][0])[q] = fsum4;
    __syncthreads();
    if (wid == 0) {
        float s = 0.f;
#pragma unroll
        for (int i = 0; i < 8; i++) s += red_s[i][t];
        atomicAdd(&g_acc[64 + t], (double)s);
    }
    __syncthreads();
    if (r == 0) reinterpret_cast<float4*>(&red_s[wid][0])[q] = fsq4;
    __syncthreads();
    if (wid == 0) {
        float s = 0.f;
#pragma unroll
        for (int i = 0; i < 8; i++) s += red_s[i][t];
        atomicAdd(&g_acc[96 + t], (double)s);
    }
}

// ---------------- K5: z = lrelu(bn(y2)) @ w_u2  (M,32)x(32,128), + column stats ----------------
__global__ void __launch_bounds__(256) kpi_u2_kernel(const float* __restrict__ w, int M) {
    __shared__ __align__(16) float w_s[4096];     // [c2][j] 32x128
    __shared__ __align__(16) float xs[8][32];
    __shared__ float red_s[2][128];
    int tid = threadIdx.x;
    for (int i = tid; i < 4096; i += 256) w_s[i] = w[i];
    int j = tid & 127, rr = tid >> 7;
    float fsum = 0.f, fsq = 0.f;
    int ntile = (M + 7) >> 3;
    for (int T = blockIdx.x; T < ntile; T += gridDim.x) {
        int base = T << 3;
        __syncthreads();
        {
            int r = tid >> 5, cc = tid & 31;
            int m = base + r;
            float v = 0.f;
            if (m < M) {
                v = g_y2[m * 32 + cc];
                v = lrelu(fmaf(v, g_aC[cc], g_cC[cc]));
            }
            xs[r][cc] = v;
        }
        __syncthreads();
        float a0 = 0.f, a1 = 0.f, a2 = 0.f, a3 = 0.f;
#pragma unroll
        for (int c2 = 0; c2 < 32; c2 += 4) {
            float4 x0 = reinterpret_cast<const float4*>(&xs[rr][0])[c2 >> 2];
            float4 x1 = reinterpret_cast<const float4*>(&xs[rr + 2][0])[c2 >> 2];
            float4 x2 = reinterpret_cast<const float4*>(&xs[rr + 4][0])[c2 >> 2];
            float4 x3 = reinterpret_cast<const float4*>(&xs[rr + 6][0])[c2 >> 2];
            float w0 = w_s[c2 * 128 + j], w1 = w_s[(c2 + 1) * 128 + j];
            float w2 = w_s[(c2 + 2) * 128 + j], w3 = w_s[(c2 + 3) * 128 + j];
            a0 = fmaf(x0.x, w0, a0); a0 = fmaf(x0.y, w1, a0); a0 = fmaf(x0.z, w2, a0); a0 = fmaf(x0.w, w3, a0);
            a1 = fmaf(x1.x, w0, a1); a1 = fmaf(x1.y, w1, a1); a1 = fmaf(x1.z, w2, a1); a1 = fmaf(x1.w, w3, a1);
            a2 = fmaf(x2.x, w0, a2); a2 = fmaf(x2.y, w1, a2); a2 = fmaf(x2.z, w2, a2); a2 = fmaf(x2.w, w3, a2);
            a3 = fmaf(x3.x, w0, a3); a3 = fmaf(x3.y, w1, a3); a3 = fmaf(x3.z, w2, a3); a3 = fmaf(x3.w, w3, a3);
        }
        int m;
        m = base + rr;     if (m < M) { g_z[m * 128 + j] = a0; fsum += a0; fsq += a0 * a0; }
        m = base + rr + 2; if (m < M) { g_z[m * 128 + j] = a1; fsum += a1; fsq += a1 * a1; }
        m = base + rr + 4; if (m < M) { g_z[m * 128 + j] = a2; fsum += a2; fsq += a2 * a2; }
        m = base + rr + 6; if (m < M) { g_z[m * 128 + j] = a3; fsum += a3; fsq += a3 * a3; }
    }
    __syncthreads();
    red_s[rr][j] = fsum; __syncthreads();
    if (rr == 0) atomicAdd(&g_acc[128 + j], (double)(red_s[0][j] + red_s[1][j]));
    __syncthreads();
    red_s[rr][j] = fsq; __syncthreads();
    if (rr == 0) atomicAdd(&g_acc[256 + j], (double)(red_s[0][j] + red_s[1][j]));
}

// ---------------- K7: out = lrelu(bn(z) + s_feats) ----------------
__global__ void kpi_final_kernel(const float* __restrict__ sf, float* __restrict__ out, int n4) {
    int i = blockIdx.x * blockDim.x + threadIdx.x;
    int stride = gridDim.x * blockDim.x;
    for (; i < n4; i += stride) {
        float4 z = reinterpret_cast<const float4*>(g_z)[i];
        float4 s = reinterpret_cast<const float4*>(sf)[i];
        int c = (i << 2) & 127;
        float4 r;
        r.x = lrelu(fmaf(z.x, g_a3[c + 0], g_c3[c + 0]) + s.x);
        r.y = lrelu(fmaf(z.y, g_a3[c + 1], g_c3[c + 1]) + s.y);
        r.z = lrelu(fmaf(z.z, g_a3[c + 2], g_c3[c + 2]) + s.z);
        r.w = lrelu(fmaf(z.w, g_a3[c + 3], g_c3[c + 3]) + s.w);
        reinterpret_cast<float4*>(out)[i] = r;
    }
}

// ---------------- launch ----------------
extern "C" void kernel_launch(void* const* d_in, const int* in_sizes, int n_in,
                              void* d_out, int out_size) {
    const float* q_pts   = (const float*)d_in[0];
    const float* s_pts   = (const float*)d_in[1];
    const float* s_feats = (const float*)d_in[2];
    const int*   nidx    = (const int*)d_in[3];
    const float* kp      = (const float*)d_in[4];
    const float* w_u1    = (const float*)d_in[5];
    const float* g_u1    = (const float*)d_in[6];
    const float* b_u1    = (const float*)d_in[7];
    const float* w_g1    = (const float*)d_in[8];
    const float* b_g1    = (const float*)d_in[9];
    const float* w_g2    = (const float*)d_in[10];
    const float* b_g2    = (const float*)d_in[11];
    const float* g_c     = (const float*)d_in[12];
    const float* b_c     = (const float*)d_in[13];
    const float* w_u2    = (const float*)d_in[14];
    const float* g_u2    = (const float*)d_in[15];
    const float* b_u2    = (const float*)d_in[16];
    float* out = (float*)d_out;

    int M = in_sizes[0] / 3;
    double invM = 1.0 / (double)M;

    kpi_u1_kernel<<<NBLK, 256>>>(s_feats, w_u1, M);
    kpi_finalize_kernel<<<1, 128>>>(0, g_u1, b_u1, invM);
    kpi_conv_kernel<<<CONVBLK, 256>>>(q_pts, s_pts, nidx, kp, w_g1, b_g1, w_g2, b_g2, M);
    kpi_finalize_kernel<<<1, 128>>>(1, g_c, b_c, invM);
    kpi_u2_kernel<<<NBLK, 256>>>(w_u2, M);
    kpi_finalize_kernel<<<1, 128>>>(2, g_u2, b_u2, invM);
    kpi_final_kernel<<<1184, 256>>>(s_feats, out, M * 32);
}